// round 4
// baseline (speedup 1.0000x reference)
#include <cuda_runtime.h>

#define N_NODES 50000
#define N_EDGES 800000
#define E_TOT   850000
#define F_IN    128
#define H1      4
#define HC1     256
#define C2      64
#define NGRAPH  500
#define NCLS    10
#define NEG     0.2f

// ---------------- scratch (device globals; no allocation allowed) ----------------
__device__ float    g_h1[N_NODES * HC1];     // layer1 pre-aggregation features [N,4,64]
__device__ float    g_out1[N_NODES * HC1];   // layer1 aggregated output
__device__ float    g_als1[N_NODES * H1];
__device__ float    g_ald1[N_NODES * H1];
__device__ float    g_e1[E_TOT * H1];        // per-edge logits -> exp numerators
__device__ unsigned g_emax1[N_NODES * H1];   // encoded float max
__device__ float    g_den1[N_NODES * H1];

__device__ float    g_h2[N_NODES * C2];
__device__ float    g_out2[N_NODES * C2];
__device__ float    g_als2[N_NODES];
__device__ float    g_ald2[N_NODES];
__device__ float    g_e2[E_TOT];
__device__ unsigned g_emax2[N_NODES];
__device__ float    g_den2[N_NODES];

__device__ float    g_pool[NGRAPH * C2];

// order-preserving float<->uint encoding for atomicMax on floats
__device__ __forceinline__ unsigned fenc(float f) {
    unsigned u = __float_as_uint(f);
    return (u & 0x80000000u) ? ~u : (u | 0x80000000u);
}
__device__ __forceinline__ float fdec(unsigned u) {
    return (u & 0x80000000u) ? __uint_as_float(u & 0x7fffffffu) : __uint_as_float(~u);
}
__device__ __forceinline__ float lrelu(float e) { return e > 0.f ? e : NEG * e; }

// ---------------- init: zero all accumulators ----------------
__global__ void k_init() {
    int stride = gridDim.x * blockDim.x;
    for (int idx = blockIdx.x * blockDim.x + threadIdx.x; idx < N_NODES * HC1; idx += stride) {
        g_out1[idx] = 0.f;
        if (idx < N_NODES * C2) g_out2[idx] = 0.f;
        if (idx < N_NODES * H1) { g_den1[idx] = 0.f; g_emax1[idx] = 0u; }
        if (idx < N_NODES)      { g_den2[idx] = 0.f; g_emax2[idx] = 0u; }
        if (idx < NGRAPH * C2)  g_pool[idx] = 0.f;
    }
}

// ---------------- GEMM1: h1 = x @ W1, fused a_src/a_dst projections ----------------
// block = (64,4): 4 nodes/block, 64 threads/node each computing 4 consecutive channels
__global__ void k_gemm1(const float* __restrict__ x, const float* __restrict__ W1,
                        const float* __restrict__ as1, const float* __restrict__ ad1) {
    __shared__ float xs[4][F_IN];
    int t = threadIdx.x, y = threadIdx.y;
    int node = blockIdx.x * 4 + y;
    xs[y][t]      = x[node * F_IN + t];
    xs[y][t + 64] = x[node * F_IN + t + 64];
    __syncthreads();
    const float4* W1v = (const float4*)W1;
    float4 acc = make_float4(0.f, 0.f, 0.f, 0.f);
#pragma unroll 8
    for (int k = 0; k < F_IN; k++) {
        float xv = xs[y][k];
        float4 w = W1v[k * 64 + t];
        acc.x += xv * w.x; acc.y += xv * w.y; acc.z += xv * w.z; acc.w += xv * w.w;
    }
    ((float4*)g_h1)[node * 64 + t] = acc;
    int c0 = 4 * t;
    float ps = acc.x * as1[c0] + acc.y * as1[c0 + 1] + acc.z * as1[c0 + 2] + acc.w * as1[c0 + 3];
    float pd = acc.x * ad1[c0] + acc.y * ad1[c0 + 1] + acc.z * ad1[c0 + 2] + acc.w * ad1[c0 + 3];
#pragma unroll
    for (int off = 8; off; off >>= 1) {
        ps += __shfl_xor_sync(0xffffffffu, ps, off, 16);
        pd += __shfl_xor_sync(0xffffffffu, pd, off, 16);
    }
    if ((t & 15) == 0) {
        int h = t >> 4;
        g_als1[node * H1 + h] = ps;
        g_ald1[node * H1 + h] = pd;
    }
}

// ---------------- layer1 edge pass A: leaky-relu logits + segment max ----------------
__global__ void k_edgeA1(const int* __restrict__ ei) {
    int idx = blockIdx.x * blockDim.x + threadIdx.x;
    if (idx >= E_TOT) return;
    int s, d;
    if (idx < N_EDGES) { s = ei[idx]; d = ei[N_EDGES + idx]; }
    else               { s = idx - N_EDGES; d = s; }
    float4 a = ((const float4*)g_als1)[s];
    float4 b = ((const float4*)g_ald1)[d];
    float4 e;
    e.x = lrelu(a.x + b.x); e.y = lrelu(a.y + b.y);
    e.z = lrelu(a.z + b.z); e.w = lrelu(a.w + b.w);
    ((float4*)g_e1)[idx] = e;
    atomicMax(&g_emax1[d * 4 + 0], fenc(e.x));
    atomicMax(&g_emax1[d * 4 + 1], fenc(e.y));
    atomicMax(&g_emax1[d * 4 + 2], fenc(e.z));
    atomicMax(&g_emax1[d * 4 + 3], fenc(e.w));
}

// ---------------- layer1 edge pass B: exp + segment denom ----------------
__global__ void k_edgeB1(const int* __restrict__ ei) {
    int idx = blockIdx.x * blockDim.x + threadIdx.x;
    if (idx >= E_TOT) return;
    int d = (idx < N_EDGES) ? ei[N_EDGES + idx] : (idx - N_EDGES);
    float4 e = ((const float4*)g_e1)[idx];
    e.x = __expf(e.x - fdec(g_emax1[d * 4 + 0]));
    e.y = __expf(e.y - fdec(g_emax1[d * 4 + 1]));
    e.z = __expf(e.z - fdec(g_emax1[d * 4 + 2]));
    e.w = __expf(e.w - fdec(g_emax1[d * 4 + 3]));
    ((float4*)g_e1)[idx] = e;
    atomicAdd(&g_den1[d * 4 + 0], e.x);
    atomicAdd(&g_den1[d * 4 + 1], e.y);
    atomicAdd(&g_den1[d * 4 + 2], e.z);
    atomicAdd(&g_den1[d * 4 + 3], e.w);
}

// ---------------- layer1 edge pass C: weighted scatter (warp per edge) ----------------
__global__ void k_edgeC1(const int* __restrict__ ei) {
    int w = (blockIdx.x * blockDim.x + threadIdx.x) >> 5;
    int lane = threadIdx.x & 31;
    if (w >= E_TOT) return;
    int s, d;
    if (w < N_EDGES) { s = ei[w]; d = ei[N_EDGES + w]; }
    else             { s = w - N_EDGES; d = s; }
    float4 ex = ((const float4*)g_e1)[w];
    float4 dn = ((const float4*)g_den1)[d];
    float alpha[4];
    alpha[0] = ex.x / (dn.x + 1e-16f);
    alpha[1] = ex.y / (dn.y + 1e-16f);
    alpha[2] = ex.z / (dn.z + 1e-16f);
    alpha[3] = ex.w / (dn.w + 1e-16f);
    const float* hs = g_h1  + (size_t)s * HC1;
    float*       od = g_out1 + (size_t)d * HC1;
#pragma unroll
    for (int j = 0; j < 8; j++) {
        int c = lane + 32 * j;
        atomicAdd(&od[c], hs[c] * alpha[c >> 6]);
    }
}

// ---------------- GEMM2: h2 = relu(out1 + b1) @ W2, fused projections ----------------
// block = (16,8): 8 nodes/block, 16 threads/node x float4
__global__ void k_gemm2(const float* __restrict__ W2, const float* __restrict__ b1,
                        const float* __restrict__ as2, const float* __restrict__ ad2) {
    __shared__ float rs[8][HC1];
    int t = threadIdx.x, y = threadIdx.y;
    int tid = t + 16 * y;
    int nodeBase = blockIdx.x * 8;
    for (int idx = tid; idx < 8 * HC1; idx += 128) {
        int nl = idx >> 8, k = idx & 255;
        float v = g_out1[(size_t)(nodeBase + nl) * HC1 + k] + b1[k];
        rs[nl][k] = v > 0.f ? v : 0.f;
    }
    __syncthreads();
    int node = nodeBase + y;
    const float4* W2v = (const float4*)W2;
    float4 acc = make_float4(0.f, 0.f, 0.f, 0.f);
#pragma unroll 8
    for (int k = 0; k < HC1; k++) {
        float rv = rs[y][k];
        float4 w = W2v[k * 16 + t];
        acc.x += rv * w.x; acc.y += rv * w.y; acc.z += rv * w.z; acc.w += rv * w.w;
    }
    ((float4*)g_h2)[node * 16 + t] = acc;
    int c0 = 4 * t;
    float ps = acc.x * as2[c0] + acc.y * as2[c0 + 1] + acc.z * as2[c0 + 2] + acc.w * as2[c0 + 3];
    float pd = acc.x * ad2[c0] + acc.y * ad2[c0 + 1] + acc.z * ad2[c0 + 2] + acc.w * ad2[c0 + 3];
#pragma unroll
    for (int off = 8; off; off >>= 1) {
        ps += __shfl_xor_sync(0xffffffffu, ps, off, 16);
        pd += __shfl_xor_sync(0xffffffffu, pd, off, 16);
    }
    if (t == 0) { g_als2[node] = ps; g_ald2[node] = pd; }
}

// ---------------- layer2 edge passes (single head) ----------------
__global__ void k_edgeA2(const int* __restrict__ ei) {
    int idx = blockIdx.x * blockDim.x + threadIdx.x;
    if (idx >= E_TOT) return;
    int s, d;
    if (idx < N_EDGES) { s = ei[idx]; d = ei[N_EDGES + idx]; }
    else               { s = idx - N_EDGES; d = s; }
    float e = lrelu(g_als2[s] + g_ald2[d]);
    g_e2[idx] = e;
    atomicMax(&g_emax2[d], fenc(e));
}

__global__ void k_edgeB2(const int* __restrict__ ei) {
    int idx = blockIdx.x * blockDim.x + threadIdx.x;
    if (idx >= E_TOT) return;
    int d = (idx < N_EDGES) ? ei[N_EDGES + idx] : (idx - N_EDGES);
    float e = __expf(g_e2[idx] - fdec(g_emax2[d]));
    g_e2[idx] = e;
    atomicAdd(&g_den2[d], e);
}

__global__ void k_edgeC2(const int* __restrict__ ei) {
    int w = (blockIdx.x * blockDim.x + threadIdx.x) >> 5;
    int lane = threadIdx.x & 31;
    if (w >= E_TOT) return;
    int s, d;
    if (w < N_EDGES) { s = ei[w]; d = ei[N_EDGES + w]; }
    else             { s = w - N_EDGES; d = s; }
    float alpha = g_e2[w] / (g_den2[d] + 1e-16f);
    const float* hs = g_h2  + (size_t)s * C2;
    float*       od = g_out2 + (size_t)d * C2;
    atomicAdd(&od[lane],      hs[lane]      * alpha);
    atomicAdd(&od[lane + 32], hs[lane + 32] * alpha);
}

// ---------------- global add pool ----------------
__global__ void k_pool(const int* __restrict__ batch, const float* __restrict__ b2) {
    int idx = blockIdx.x * blockDim.x + threadIdx.x;
    if (idx >= N_NODES * C2) return;
    int n = idx >> 6, c = idx & 63;
    int g = batch[n];
    atomicAdd(&g_pool[g * C2 + c], g_out2[idx] + b2[c]);
}

// ---------------- classifier + log_softmax ----------------
__global__ void k_cls(const float* __restrict__ fcw, const float* __restrict__ fcb,
                      float* __restrict__ out) {
    int g = blockIdx.x;
    int t = threadIdx.x;
    __shared__ float lg[NCLS];
    __shared__ float s_m, s_lse;
    if (t < NCLS) {
        float acc = fcb[t];
#pragma unroll
        for (int k = 0; k < C2; k++) acc += g_pool[g * C2 + k] * fcw[k * NCLS + t];
        lg[t] = acc;
    }
    __syncthreads();
    if (t == 0) {
        float m = lg[0];
        for (int i = 1; i < NCLS; i++) m = fmaxf(m, lg[i]);
        float s = 0.f;
        for (int i = 0; i < NCLS; i++) s += expf(lg[i] - m);
        s_m = m; s_lse = logf(s);
    }
    __syncthreads();
    if (t < NCLS) out[g * NCLS + t] = lg[t] - s_m - s_lse;
}

// ---------------- launch ----------------
extern "C" void kernel_launch(void* const* d_in, const int* in_sizes, int n_in,
                              void* d_out, int out_size) {
    const float* x    = (const float*)d_in[0];
    const int*   ei   = (const int*)d_in[1];
    const int*   bat  = (const int*)d_in[2];
    const float* W1   = (const float*)d_in[3];
    const float* as1  = (const float*)d_in[4];
    const float* ad1  = (const float*)d_in[5];
    const float* b1   = (const float*)d_in[6];
    const float* W2   = (const float*)d_in[7];
    const float* as2  = (const float*)d_in[8];
    const float* ad2  = (const float*)d_in[9];
    const float* b2   = (const float*)d_in[10];
    const float* fcw  = (const float*)d_in[11];
    const float* fcb  = (const float*)d_in[12];
    float* out = (float*)d_out;

    k_init<<<2048, 256>>>();
    k_gemm1<<<N_NODES / 4, dim3(64, 4)>>>(x, W1, as1, ad1);
    int eb = (E_TOT + 255) / 256;
    k_edgeA1<<<eb, 256>>>(ei);
    k_edgeB1<<<eb, 256>>>(ei);
    k_edgeC1<<<(E_TOT * 32 + 255) / 256, 256>>>(ei);
    k_gemm2<<<N_NODES / 8, dim3(16, 8)>>>(W2, b1, as2, ad2);
    k_edgeA2<<<eb, 256>>>(ei);
    k_edgeB2<<<eb, 256>>>(ei);
    k_edgeC2<<<(E_TOT * 32 + 255) / 256, 256>>>(ei);
    k_pool<<<(N_NODES * C2 + 255) / 256, 256>>>(bat, b2);
    k_cls<<<NGRAPH, 32>>>(fcw, fcb, out);
}

// round 6
// speedup vs baseline: 1.2791x; 1.2791x over previous
#include <cuda_runtime.h>

#define N_NODES 50000
#define N_EDGES 800000
#define E_TOT   850000
#define F_IN    128
#define H1      4
#define HC1     256
#define C2      64
#define NGRAPH  500
#define NCLS    10
#define NEG     0.2f

// ---------------- scratch (device globals; no allocation allowed) ----------------
__device__ __align__(16) float    g_h1[N_NODES * HC1];
__device__ __align__(16) float    g_out1[N_NODES * HC1];
__device__ __align__(16) float    g_als1[N_NODES * H1];
__device__ __align__(16) float    g_ald1[N_NODES * H1];
__device__ __align__(16) float    g_e1[E_TOT * H1];
__device__ __align__(16) unsigned g_emax1[N_NODES * H1];
__device__ __align__(16) float    g_den1[N_NODES * H1];

__device__ __align__(16) float    g_h2[N_NODES * C2];
__device__ __align__(16) float    g_out2[N_NODES * C2];
__device__ __align__(16) float    g_als2[N_NODES];
__device__ __align__(16) float    g_ald2[N_NODES];
__device__ __align__(16) float    g_e2[E_TOT];
__device__ __align__(16) unsigned g_emax2[N_NODES];
__device__ __align__(16) float    g_den2[N_NODES];

__device__ __align__(16) float    g_pool[NGRAPH * C2];

// vector reduction: one L2 atomic op per 16 bytes (sm_90+)
__device__ __forceinline__ void red_add_v4(float* addr, float4 v) {
    asm volatile("red.global.add.v4.f32 [%0], {%1,%2,%3,%4};"
                 :: "l"(addr), "f"(v.x), "f"(v.y), "f"(v.z), "f"(v.w) : "memory");
}

// order-preserving float<->uint encoding for atomicMax on floats
__device__ __forceinline__ unsigned fenc(float f) {
    unsigned u = __float_as_uint(f);
    return (u & 0x80000000u) ? ~u : (u | 0x80000000u);
}
__device__ __forceinline__ float fdec(unsigned u) {
    return (u & 0x80000000u) ? __uint_as_float(u & 0x7fffffffu) : __uint_as_float(~u);
}
__device__ __forceinline__ float lrelu(float e) { return e > 0.f ? e : NEG * e; }

// ---------------- init: zero all accumulators ----------------
__global__ void k_init() {
    int stride = gridDim.x * blockDim.x;
    for (int idx = blockIdx.x * blockDim.x + threadIdx.x; idx < N_NODES * HC1; idx += stride) {
        g_out1[idx] = 0.f;
        if (idx < N_NODES * C2) g_out2[idx] = 0.f;
        if (idx < N_NODES * H1) { g_den1[idx] = 0.f; g_emax1[idx] = 0u; }
        if (idx < N_NODES)      { g_den2[idx] = 0.f; g_emax2[idx] = 0u; }
        if (idx < NGRAPH * C2)  g_pool[idx] = 0.f;
    }
}

// ---------------- GEMM1: h1 = x @ W1, fused a_src/a_dst projections ----------------
__global__ void k_gemm1(const float* __restrict__ x, const float* __restrict__ W1,
                        const float* __restrict__ as1, const float* __restrict__ ad1) {
    __shared__ float xs[4][F_IN];
    int t = threadIdx.x, y = threadIdx.y;
    int node = blockIdx.x * 4 + y;
    xs[y][t]      = x[node * F_IN + t];
    xs[y][t + 64] = x[node * F_IN + t + 64];
    __syncthreads();
    const float4* W1v = (const float4*)W1;
    float4 acc = make_float4(0.f, 0.f, 0.f, 0.f);
#pragma unroll 8
    for (int k = 0; k < F_IN; k++) {
        float xv = xs[y][k];
        float4 w = W1v[k * 64 + t];
        acc.x += xv * w.x; acc.y += xv * w.y; acc.z += xv * w.z; acc.w += xv * w.w;
    }
    ((float4*)g_h1)[node * 64 + t] = acc;
    int c0 = 4 * t;
    float ps = acc.x * as1[c0] + acc.y * as1[c0 + 1] + acc.z * as1[c0 + 2] + acc.w * as1[c0 + 3];
    float pd = acc.x * ad1[c0] + acc.y * ad1[c0 + 1] + acc.z * ad1[c0 + 2] + acc.w * ad1[c0 + 3];
#pragma unroll
    for (int off = 8; off; off >>= 1) {
        ps += __shfl_xor_sync(0xffffffffu, ps, off, 16);
        pd += __shfl_xor_sync(0xffffffffu, pd, off, 16);
    }
    if ((t & 15) == 0) {
        int h = t >> 4;
        g_als1[node * H1 + h] = ps;
        g_ald1[node * H1 + h] = pd;
    }
}

// ---------------- layer1 edge pass A: leaky-relu logits + segment max ----------------
__global__ void k_edgeA1(const int* __restrict__ ei) {
    int idx = blockIdx.x * blockDim.x + threadIdx.x;
    if (idx >= E_TOT) return;
    int s, d;
    if (idx < N_EDGES) { s = ei[idx]; d = ei[N_EDGES + idx]; }
    else               { s = idx - N_EDGES; d = s; }
    float4 a = ((const float4*)g_als1)[s];
    float4 b = ((const float4*)g_ald1)[d];
    float4 e;
    e.x = lrelu(a.x + b.x); e.y = lrelu(a.y + b.y);
    e.z = lrelu(a.z + b.z); e.w = lrelu(a.w + b.w);
    ((float4*)g_e1)[idx] = e;
    atomicMax(&g_emax1[d * 4 + 0], fenc(e.x));
    atomicMax(&g_emax1[d * 4 + 1], fenc(e.y));
    atomicMax(&g_emax1[d * 4 + 2], fenc(e.z));
    atomicMax(&g_emax1[d * 4 + 3], fenc(e.w));
}

// ---------------- layer1 edge pass B: exp + segment denom (vector red) ----------------
__global__ void k_edgeB1(const int* __restrict__ ei) {
    int idx = blockIdx.x * blockDim.x + threadIdx.x;
    if (idx >= E_TOT) return;
    int d = (idx < N_EDGES) ? ei[N_EDGES + idx] : (idx - N_EDGES);
    float4 e = ((const float4*)g_e1)[idx];
    e.x = __expf(e.x - fdec(g_emax1[d * 4 + 0]));
    e.y = __expf(e.y - fdec(g_emax1[d * 4 + 1]));
    e.z = __expf(e.z - fdec(g_emax1[d * 4 + 2]));
    e.w = __expf(e.w - fdec(g_emax1[d * 4 + 3]));
    ((float4*)g_e1)[idx] = e;
    red_add_v4(&g_den1[d * 4], e);
}

// ---------------- layer1 edge pass C: weighted scatter (warp/edge, v4 red) ----------------
__global__ void k_edgeC1(const int* __restrict__ ei) {
    int w = (blockIdx.x * blockDim.x + threadIdx.x) >> 5;
    int lane = threadIdx.x & 31;
    if (w >= E_TOT) return;
    int s, d;
    if (w < N_EDGES) { s = ei[w]; d = ei[N_EDGES + w]; }
    else             { s = w - N_EDGES; d = s; }
    float4 ex = ((const float4*)g_e1)[w];
    float4 dn = ((const float4*)g_den1)[d];
    float alpha[4];
    alpha[0] = ex.x / (dn.x + 1e-16f);
    alpha[1] = ex.y / (dn.y + 1e-16f);
    alpha[2] = ex.z / (dn.z + 1e-16f);
    alpha[3] = ex.w / (dn.w + 1e-16f);
    const float4* hs = (const float4*)(g_h1 + (size_t)s * HC1);
    float*        od = g_out1 + (size_t)d * HC1;
    // float4 j covers channels [4j,4j+3]; head = j>>4
    {
        float a0 = alpha[lane >> 4];
        float4 h = hs[lane];
        h.x *= a0; h.y *= a0; h.z *= a0; h.w *= a0;
        red_add_v4(od + 4 * lane, h);
    }
    {
        float a1 = alpha[(lane + 32) >> 4];
        float4 h = hs[lane + 32];
        h.x *= a1; h.y *= a1; h.z *= a1; h.w *= a1;
        red_add_v4(od + 4 * (lane + 32), h);
    }
}

// ---------------- GEMM2: h2 = relu(out1 + b1) @ W2, fused projections ----------------
__global__ void k_gemm2(const float* __restrict__ W2, const float* __restrict__ b1,
                        const float* __restrict__ as2, const float* __restrict__ ad2) {
    __shared__ float rs[8][HC1];
    int t = threadIdx.x, y = threadIdx.y;
    int tid = t + 16 * y;
    int nodeBase = blockIdx.x * 8;
    for (int idx = tid; idx < 8 * HC1; idx += 128) {
        int nl = idx >> 8, k = idx & 255;
        float v = g_out1[(size_t)(nodeBase + nl) * HC1 + k] + b1[k];
        rs[nl][k] = v > 0.f ? v : 0.f;
    }
    __syncthreads();
    int node = nodeBase + y;
    const float4* W2v = (const float4*)W2;
    float4 acc = make_float4(0.f, 0.f, 0.f, 0.f);
#pragma unroll 8
    for (int k = 0; k < HC1; k++) {
        float rv = rs[y][k];
        float4 w = W2v[k * 16 + t];
        acc.x += rv * w.x; acc.y += rv * w.y; acc.z += rv * w.z; acc.w += rv * w.w;
    }
    ((float4*)g_h2)[node * 16 + t] = acc;
    int c0 = 4 * t;
    float ps = acc.x * as2[c0] + acc.y * as2[c0 + 1] + acc.z * as2[c0 + 2] + acc.w * as2[c0 + 3];
    float pd = acc.x * ad2[c0] + acc.y * ad2[c0 + 1] + acc.z * ad2[c0 + 2] + acc.w * ad2[c0 + 3];
#pragma unroll
    for (int off = 8; off; off >>= 1) {
        ps += __shfl_xor_sync(0xffffffffu, ps, off, 16);
        pd += __shfl_xor_sync(0xffffffffu, pd, off, 16);
    }
    if (t == 0) { g_als2[node] = ps; g_ald2[node] = pd; }
}

// ---------------- layer2 edge passes (single head) ----------------
__global__ void k_edgeA2(const int* __restrict__ ei) {
    int idx = blockIdx.x * blockDim.x + threadIdx.x;
    if (idx >= E_TOT) return;
    int s, d;
    if (idx < N_EDGES) { s = ei[idx]; d = ei[N_EDGES + idx]; }
    else               { s = idx - N_EDGES; d = s; }
    float e = lrelu(g_als2[s] + g_ald2[d]);
    g_e2[idx] = e;
    atomicMax(&g_emax2[d], fenc(e));
}

__global__ void k_edgeB2(const int* __restrict__ ei) {
    int idx = blockIdx.x * blockDim.x + threadIdx.x;
    if (idx >= E_TOT) return;
    int d = (idx < N_EDGES) ? ei[N_EDGES + idx] : (idx - N_EDGES);
    float e = __expf(g_e2[idx] - fdec(g_emax2[d]));
    g_e2[idx] = e;
    atomicAdd(&g_den2[d], e);
}

// 16 lanes per edge, 2 edges per warp, v4 red
__global__ void k_edgeC2(const int* __restrict__ ei) {
    int gwarp = (blockIdx.x * blockDim.x + threadIdx.x) >> 5;
    int lane = threadIdx.x & 31;
    int w = gwarp * 2 + (lane >> 4);
    int l16 = lane & 15;
    if (w >= E_TOT) return;
    int s, d;
    if (w < N_EDGES) { s = ei[w]; d = ei[N_EDGES + w]; }
    else             { s = w - N_EDGES; d = s; }
    float alpha = g_e2[w] / (g_den2[d] + 1e-16f);
    float4 h = ((const float4*)(g_h2 + (size_t)s * C2))[l16];
    h.x *= alpha; h.y *= alpha; h.z *= alpha; h.w *= alpha;
    red_add_v4(g_out2 + (size_t)d * C2 + 4 * l16, h);
}

// ---------------- global add pool (v4 red) ----------------
__global__ void k_pool(const int* __restrict__ batch, const float* __restrict__ b2) {
    int idx = blockIdx.x * blockDim.x + threadIdx.x;  // over N_NODES*16 float4s
    if (idx >= N_NODES * 16) return;
    int n = idx >> 4, c4 = idx & 15;
    int g = batch[n];
    float4 v = ((const float4*)g_out2)[idx];
    float4 bb = ((const float4*)b2)[c4];
    v.x += bb.x; v.y += bb.y; v.z += bb.z; v.w += bb.w;
    red_add_v4(g_pool + g * C2 + 4 * c4, v);
}

// ---------------- classifier + log_softmax ----------------
__global__ void k_cls(const float* __restrict__ fcw, const float* __restrict__ fcb,
                      float* __restrict__ out) {
    int g = blockIdx.x;
    int t = threadIdx.x;
    __shared__ float lg[NCLS];
    __shared__ float s_m, s_lse;
    if (t < NCLS) {
        float acc = fcb[t];
#pragma unroll
        for (int k = 0; k < C2; k++) acc += g_pool[g * C2 + k] * fcw[k * NCLS + t];
        lg[t] = acc;
    }
    __syncthreads();
    if (t == 0) {
        float m = lg[0];
        for (int i = 1; i < NCLS; i++) m = fmaxf(m, lg[i]);
        float s = 0.f;
        for (int i = 0; i < NCLS; i++) s += expf(lg[i] - m);
        s_m = m; s_lse = logf(s);
    }
    __syncthreads();
    if (t < NCLS) out[g * NCLS + t] = lg[t] - s_m - s_lse;
}

// ---------------- launch ----------------
extern "C" void kernel_launch(void* const* d_in, const int* in_sizes, int n_in,
                              void* d_out, int out_size) {
    const float* x    = (const float*)d_in[0];
    const int*   ei   = (const int*)d_in[1];
    const int*   bat  = (const int*)d_in[2];
    const float* W1   = (const float*)d_in[3];
    const float* as1  = (const float*)d_in[4];
    const float* ad1  = (const float*)d_in[5];
    const float* b1   = (const float*)d_in[6];
    const float* W2   = (const float*)d_in[7];
    const float* as2  = (const float*)d_in[8];
    const float* ad2  = (const float*)d_in[9];
    const float* b2   = (const float*)d_in[10];
    const float* fcw  = (const float*)d_in[11];
    const float* fcb  = (const float*)d_in[12];
    float* out = (float*)d_out;

    k_init<<<2048, 256>>>();
    k_gemm1<<<N_NODES / 4, dim3(64, 4)>>>(x, W1, as1, ad1);
    int eb = (E_TOT + 255) / 256;
    k_edgeA1<<<eb, 256>>>(ei);
    k_edgeB1<<<eb, 256>>>(ei);
    k_edgeC1<<<(E_TOT * 32 + 255) / 256, 256>>>(ei);
    k_gemm2<<<N_NODES / 8, dim3(16, 8)>>>(W2, b1, as2, ad2);
    k_edgeA2<<<eb, 256>>>(ei);
    k_edgeB2<<<eb, 256>>>(ei);
    k_edgeC2<<<((E_TOT + 1) / 2 * 32 + 255) / 256, 256>>>(ei);
    k_pool<<<(N_NODES * 16 + 255) / 256, 256>>>(bat, b2);
    k_cls<<<NGRAPH, 32>>>(fcw, fcb, out);
}